// round 2
// baseline (speedup 1.0000x reference)
#include <cuda_runtime.h>
#include <cstdint>

// Problem constants
#define NN 32768          // B*K = 64*512 rows
#define DD 256            // embedding dim
#define EE 1024           // num embeddings
#define DECAY 0.99f
#define ONE_MINUS_DECAY 0.01f
#define EPSV 1e-5f

// Output layout (concatenated f32, reference tuple order):
// z_q [N*D], vq_loss [1], indices [N], new_codebook [E*D], new_cluster_size [E], new_embed_sum [E*D]
#define OFF_ZQ   0
#define OFF_LOSS 8388608
#define OFF_IDX  8388609
#define OFF_CB   8421377
#define OFF_CS   8683521
#define OFF_ES   8684545

// -------- scratch (no allocations allowed) --------
__device__ float g_csq[EE];
__device__ int   g_indices[NN];
__device__ float g_batch_cs[EE];
__device__ float g_batch_es[EE * DD];
__device__ float g_loss;
__device__ float g_ncs[EE];
__device__ float g_n;

// -------- f32x2 packed helpers (sm_100+ PTX) --------
__device__ __forceinline__ unsigned long long pack2(float a, float b) {
    unsigned long long r;
    asm("mov.b64 %0, {%1, %2};" : "=l"(r) : "f"(a), "f"(b));
    return r;
}
__device__ __forceinline__ void fma2(unsigned long long& d, unsigned long long a, unsigned long long b) {
    asm("fma.rn.f32x2 %0, %1, %2, %0;" : "+l"(d) : "l"(a), "l"(b));
}
__device__ __forceinline__ float2 unpack2(unsigned long long v) {
    float2 r;
    asm("mov.b64 {%0, %1}, %2;" : "=f"(r.x), "=f"(r.y) : "l"(v));
    return r;
}

// -------- K0: zero scratch --------
__global__ void zero_kernel() {
    int i = blockIdx.x * blockDim.x + threadIdx.x;
    if (i < EE * DD) g_batch_es[i] = 0.0f;
    if (i < EE) g_batch_cs[i] = 0.0f;
    if (i == 0) g_loss = 0.0f;
}

// -------- K0b: codebook squared norms --------
__global__ void csq_kernel(const float* __restrict__ cb) {
    int e = blockIdx.x;
    int lane = threadIdx.x;
    const float4* row = (const float4*)(cb + (size_t)e * DD);
    float4 a = row[lane];
    float4 b = row[lane + 32];
    float s = a.x * a.x + a.y * a.y + a.z * a.z + a.w * a.w
            + b.x * b.x + b.y * b.y + b.z * b.z + b.w * b.w;
    #pragma unroll
    for (int off = 16; off > 0; off >>= 1)
        s += __shfl_xor_sync(0xFFFFFFFFu, s, off);
    if (lane == 0) g_csq[e] = s;
}

// -------- K1: fused distance GEMM + argmin --------
// Block: 128 rows x full E (looped in 128-col tiles). 256 threads = 16x16,
// each thread 8 rows x 8 cols, K-chunks of 16, packed f32x2 FMA.
#define TM 128
#define TN 128
#define TKC 16

__global__ __launch_bounds__(256, 2)
void dist_kernel(const float* __restrict__ z_e, const float* __restrict__ cb) {
    // row stride (TM+4)=132 floats = 528 B (multiple of 16) -> float4 reads
    // stay aligned as long as the base is 16B-aligned.
    __shared__ __align__(16) float x_s[TKC][TM + 4];
    __shared__ __align__(16) float c_s[TKC][TN + 4];
    __shared__ float csq_s[TN];
    __shared__ float red_v[TM][16];
    __shared__ int   red_i[TM][16];

    const int tid = threadIdx.x;
    const int tx = tid & 15, ty = tid >> 4;
    const int row0 = blockIdx.x * TM;

    float bestv[8];
    int   besti[8];
    #pragma unroll
    for (int r = 0; r < 8; r++) { bestv[r] = 3.4e38f; besti[r] = 0; }

    for (int e0 = 0; e0 < EE; e0 += TN) {
        __syncthreads();   // protect csq_s from prior iteration's readers
        if (tid < TN) csq_s[tid] = g_csq[e0 + tid];

        unsigned long long acc[8][4];
        #pragma unroll
        for (int r = 0; r < 8; r++)
            #pragma unroll
            for (int j = 0; j < 4; j++) acc[r][j] = 0ull;

        for (int k0 = 0; k0 < DD; k0 += TKC) {
            __syncthreads();
            #pragma unroll
            for (int it = 0; it < 2; it++) {
                int i = tid + it * 256;        // 512 float4 slots per tile
                int rr = i >> 2;
                int kq = (i & 3) << 2;
                float4 v = *(const float4*)(z_e + (size_t)(row0 + rr) * DD + k0 + kq);
                x_s[kq + 0][rr] = v.x; x_s[kq + 1][rr] = v.y;
                x_s[kq + 2][rr] = v.z; x_s[kq + 3][rr] = v.w;
                float4 w = *(const float4*)(cb + (size_t)(e0 + rr) * DD + k0 + kq);
                c_s[kq + 0][rr] = w.x; c_s[kq + 1][rr] = w.y;
                c_s[kq + 2][rr] = w.z; c_s[kq + 3][rr] = w.w;
            }
            __syncthreads();

            #pragma unroll
            for (int kk = 0; kk < TKC; kk++) {
                const float4 xa = *(const float4*)&x_s[kk][ty * 8];
                const float4 xb = *(const float4*)&x_s[kk][ty * 8 + 4];
                const float4 ca = *(const float4*)&c_s[kk][tx * 8];
                const float4 cc = *(const float4*)&c_s[kk][tx * 8 + 4];
                unsigned long long cp0 = pack2(ca.x, ca.y);
                unsigned long long cp1 = pack2(ca.z, ca.w);
                unsigned long long cp2 = pack2(cc.x, cc.y);
                unsigned long long cp3 = pack2(cc.z, cc.w);
                float xr[8] = {xa.x, xa.y, xa.z, xa.w, xb.x, xb.y, xb.z, xb.w};
                #pragma unroll
                for (int r = 0; r < 8; r++) {
                    unsigned long long xp = pack2(xr[r], xr[r]);
                    fma2(acc[r][0], xp, cp0);
                    fma2(acc[r][1], xp, cp1);
                    fma2(acc[r][2], xp, cp2);
                    fma2(acc[r][3], xp, cp3);
                }
            }
        }

        // scores + running argmin (ascending column order for tie-breaking)
        #pragma unroll
        for (int r = 0; r < 8; r++) {
            #pragma unroll
            for (int j = 0; j < 4; j++) {
                float2 d = unpack2(acc[r][j]);
                int lc = tx * 8 + 2 * j;
                float s0 = csq_s[lc]     - 2.0f * d.x;
                float s1 = csq_s[lc + 1] - 2.0f * d.y;
                if (s0 < bestv[r]) { bestv[r] = s0; besti[r] = e0 + lc; }
                if (s1 < bestv[r]) { bestv[r] = s1; besti[r] = e0 + lc + 1; }
            }
        }
    }

    #pragma unroll
    for (int r = 0; r < 8; r++) {
        red_v[ty * 8 + r][tx] = bestv[r];
        red_i[ty * 8 + r][tx] = besti[r];
    }
    __syncthreads();
    if (tid < TM) {
        float bv = red_v[tid][0];
        int   bi = red_i[tid][0];
        #pragma unroll
        for (int t = 1; t < 16; t++) {
            float v = red_v[tid][t];
            int   ii = red_i[tid][t];
            if (v < bv || (v == bv && ii < bi)) { bv = v; bi = ii; }
        }
        g_indices[row0 + tid] = bi;
    }
}

// -------- K2: gather z_q, commitment loss, scatter EMA stats --------
__global__ void gather_kernel(const float* __restrict__ z_e,
                              const float* __restrict__ cb,
                              float* __restrict__ out) {
    __shared__ float warp_loss[8];
    const int warp = threadIdx.x >> 5;
    const int lane = threadIdx.x & 31;
    const int row = blockIdx.x * 8 + warp;

    const int idx = g_indices[row];
    const float4* crow = (const float4*)(cb + (size_t)idx * DD);
    const float4* xrow = (const float4*)(z_e + (size_t)row * DD);
    float4* zqrow = (float4*)(out + OFF_ZQ + (size_t)row * DD);
    float* es = g_batch_es + (size_t)idx * DD;

    float lsum = 0.0f;
    #pragma unroll
    for (int j = 0; j < 2; j++) {
        int q = lane + j * 32;                    // float4 index, 64 per row
        float4 c = crow[q];
        float4 x = xrow[q];
        // straight-through: z_e + (z_q - z_e), matches reference op order
        float4 o;
        o.x = x.x + (c.x - x.x); o.y = x.y + (c.y - x.y);
        o.z = x.z + (c.z - x.z); o.w = x.w + (c.w - x.w);
        zqrow[q] = o;
        float dx = x.x - c.x, dy = x.y - c.y, dz = x.z - c.z, dw = x.w - c.w;
        lsum += dx * dx + dy * dy + dz * dz + dw * dw;
        atomicAdd(&es[q * 4 + 0], x.x);
        atomicAdd(&es[q * 4 + 1], x.y);
        atomicAdd(&es[q * 4 + 2], x.z);
        atomicAdd(&es[q * 4 + 3], x.w);
    }
    if (lane == 0) {
        atomicAdd(&g_batch_cs[idx], 1.0f);
        out[OFF_IDX + row] = (float)idx;
    }
    #pragma unroll
    for (int off = 16; off > 0; off >>= 1)
        lsum += __shfl_xor_sync(0xFFFFFFFFu, lsum, off);
    if (lane == 0) warp_loss[warp] = lsum;
    __syncthreads();
    if (threadIdx.x == 0) {
        float s = 0.0f;
        #pragma unroll
        for (int w = 0; w < 8; w++) s += warp_loss[w];
        atomicAdd(&g_loss, s);
    }
}

// -------- K3a: new_cluster_size, n, vq_loss --------
__global__ void fin1_kernel(const float* __restrict__ ema_cs, float* __restrict__ out) {
    __shared__ float red[1024];
    int t = threadIdx.x;
    float ncs = DECAY * ema_cs[t] + ONE_MINUS_DECAY * g_batch_cs[t];
    out[OFF_CS + t] = ncs;
    g_ncs[t] = ncs;
    red[t] = ncs;
    __syncthreads();
    for (int s = 512; s > 0; s >>= 1) {
        if (t < s) red[t] += red[t + s];
        __syncthreads();
    }
    if (t == 0) {
        g_n = red[0];
        out[OFF_LOSS] = 0.5f * g_loss / 8388608.0f;
    }
}

// -------- K3b: new_embed_sum + new_codebook --------
// NOTE: out + OFF_CB / OFF_ES are ODD element offsets (loss occupies 1 slot),
// so output stores must be scalar. Inputs/scratch stay vectorized.
__global__ void fin2_kernel(const float* __restrict__ ema_es, float* __restrict__ out) {
    int e = blockIdx.x;
    float n = g_n;
    float sm = (g_ncs[e] + EPSV) / (n + (float)EE * EPSV) * n;
    int d = threadIdx.x * 4;
    size_t base = (size_t)e * DD + d;
    float4 ema4 = *(const float4*)(ema_es + base);
    float4 bat4 = *(const float4*)(g_batch_es + base);
    float nes[4];
    nes[0] = DECAY * ema4.x + ONE_MINUS_DECAY * bat4.x;
    nes[1] = DECAY * ema4.y + ONE_MINUS_DECAY * bat4.y;
    nes[2] = DECAY * ema4.z + ONE_MINUS_DECAY * bat4.z;
    nes[3] = DECAY * ema4.w + ONE_MINUS_DECAY * bat4.w;
    float* o_es = out + OFF_ES + base;
    float* o_cb = out + OFF_CB + base;
    #pragma unroll
    for (int j = 0; j < 4; j++) {
        o_es[j] = nes[j];
        o_cb[j] = nes[j] / sm;
    }
}

extern "C" void kernel_launch(void* const* d_in, const int* in_sizes, int n_in,
                              void* d_out, int out_size) {
    const float* z_e    = (const float*)d_in[0];
    const float* cb     = (const float*)d_in[1];
    const float* ema_cs = (const float*)d_in[2];
    const float* ema_es = (const float*)d_in[3];
    float* out = (float*)d_out;

    zero_kernel<<<(EE * DD + 255) / 256, 256>>>();
    csq_kernel<<<EE, 32>>>(cb);
    dist_kernel<<<NN / TM, 256>>>(z_e, cb);
    gather_kernel<<<NN / 8, 256>>>(z_e, cb, out);
    fin1_kernel<<<1, 1024>>>(ema_cs, out);
    fin2_kernel<<<EE, DD / 4>>>(ema_es, out);
}